// round 4
// baseline (speedup 1.0000x reference)
#include <cuda_runtime.h>
#include <stdint.h>

#define BB   8
#define NA   3
#define NC   80
#define HH   160
#define WW   160
#define HW   (HH*WW)        // 25600
#define NN   (NA*HW)        // 76800
#define TOPK 100
#define NBINS 2048
#define CAP  1024

// ---------------- device scratch (no allocations allowed) ----------------
__device__ float    g_scores[BB*NN];
__device__ uint8_t  g_cls[BB*NN];

__device__ __forceinline__ float sigmoidf_(float x) {
    return 1.0f / (1.0f + expf(-x));
}

// warp-aggregated shared-memory histogram increment
__device__ __forceinline__ void hist_add(int* sh, unsigned bin) {
    unsigned peers = __match_any_sync(0xFFFFFFFFu, bin);
    int leader = __ffs(peers) - 1;
    if ((int)(threadIdx.x & 31) == leader)
        atomicAdd(&sh[bin], __popc(peers));
}

// ---------------- kernel 1: per-cell score + argmax class (pure streaming) ----------------
__global__ void __launch_bounds__(256) score_kernel(const float* __restrict__ obj,
                                                    const float* __restrict__ quality,
                                                    const float* __restrict__ cls) {
    int t  = blockIdx.x * blockDim.x + threadIdx.x;    // quad index over B*N/4
    int c0 = t * 4;                                    // base cell index
    if (c0 >= BB * NN) return;
    int b   = c0 / NN;
    int r   = c0 - b * NN;
    int a   = r / HW;
    int pix = r - a * HW;                              // multiple of 4

    const float4* cbase = (const float4*)(cls + ((size_t)(b * NA + a) * NC) * HW + pix);
    float m0 = -1e30f, m1 = -1e30f, m2 = -1e30f, m3 = -1e30f;
    int   i0 = 0, i1 = 0, i2 = 0, i3 = 0;
    #pragma unroll 8
    for (int c = 0; c < NC; c++) {
        float4 v = cbase[c * (HW / 4)];
        if (v.x > m0) { m0 = v.x; i0 = c; }
        if (v.y > m1) { m1 = v.y; i1 = c; }
        if (v.z > m2) { m2 = v.z; i2 = c; }
        if (v.w > m3) { m3 = v.w; i3 = c; }
    }

    int oq = (b * NA + a) * HW + pix;
    float4 ov = *(const float4*)(obj + oq);
    float4 qv = *(const float4*)(quality + oq);

    float4 s;
    s.x = sigmoidf_(ov.x) * sigmoidf_(qv.x) * sigmoidf_(m0);
    s.y = sigmoidf_(ov.y) * sigmoidf_(qv.y) * sigmoidf_(m1);
    s.z = sigmoidf_(ov.z) * sigmoidf_(qv.z) * sigmoidf_(m2);
    s.w = sigmoidf_(ov.w) * sigmoidf_(qv.w) * sigmoidf_(m3);

    *(float4*)(g_scores + c0) = s;
    *(uchar4*)(g_cls + c0) = make_uchar4((uint8_t)i0, (uint8_t)i1, (uint8_t)i2, (uint8_t)i3);
}

// ---------------- kernel 2: per-batch top-100 + box decode ----------------
__global__ void __launch_bounds__(1024) topk_kernel(const float* __restrict__ box,
                                                    const float* __restrict__ anchors,
                                                    float* __restrict__ out) {
    __shared__ int                sh[NBINS];
    __shared__ unsigned long long buf[CAP];
    __shared__ int s_cnt, s_t, s_chi, s_tot, s_u;

    int b   = blockIdx.x;
    int tid = threadIdx.x;
    const float4* sc4 = (const float4*)(g_scores + (size_t)b * NN);
    const float*  sc  = g_scores + (size_t)b * NN;

    // ---- pass A: level-1 histogram (top 11 bits), warp-aggregated ----
    sh[tid] = 0; sh[tid + 1024] = 0;
    __syncthreads();
    for (int i = tid; i < NN / 4; i += 1024) {
        float4 v = sc4[i];
        hist_add(sh, __float_as_uint(v.x) >> 21);
        hist_add(sh, __float_as_uint(v.y) >> 21);
        hist_add(sh, __float_as_uint(v.z) >> 21);
        hist_add(sh, __float_as_uint(v.w) >> 21);
    }
    __syncthreads();

    // ---- parallel inclusive suffix scan (Hillis-Steele) ----
    #pragma unroll
    for (int d = 1; d < NBINS; d <<= 1) {
        int v0 = (tid + d < NBINS) ? sh[tid + d] : 0;
        int v1 = (tid + 1024 + d < NBINS) ? sh[tid + 1024 + d] : 0;
        __syncthreads();
        sh[tid] += v0;
        sh[tid + 1024] += v1;
        __syncthreads();
    }
    // crossing bin: largest i with S[i] >= TOPK
    {
        int i = tid;
        if (sh[i] >= TOPK && (i == NBINS - 1 || sh[i + 1] < TOPK)) {
            s_t = i; s_tot = sh[i]; s_chi = (i < NBINS - 1) ? sh[i + 1] : 0;
        }
        i = tid + 1024;
        if (sh[i] >= TOPK && (i == NBINS - 1 || sh[i + 1] < TOPK)) {
            s_t = i; s_tot = sh[i]; s_chi = (i < NBINS - 1) ? sh[i + 1] : 0;
        }
        if (tid == 0) s_cnt = 0;
    }
    __syncthreads();
    unsigned t1 = (unsigned)s_t;
    int cnt_tot = s_tot;
    int chi     = s_chi;

    if (cnt_tot <= CAP) {
        // ---- FAST PATH: candidate count fits; single float4 collect scan ----
        for (int i = tid; i < NN / 4; i += 1024) {
            float4 v = sc4[i];
            unsigned bx = __float_as_uint(v.x);
            unsigned by = __float_as_uint(v.y);
            unsigned bz = __float_as_uint(v.z);
            unsigned bw = __float_as_uint(v.w);
            int base = i * 4;
            if ((bx >> 21) >= t1) buf[atomicAdd(&s_cnt, 1)] = (((unsigned long long)bx) << 17) | (unsigned long long)(0x1FFFFu - (unsigned)(base + 0));
            if ((by >> 21) >= t1) buf[atomicAdd(&s_cnt, 1)] = (((unsigned long long)by) << 17) | (unsigned long long)(0x1FFFFu - (unsigned)(base + 1));
            if ((bz >> 21) >= t1) buf[atomicAdd(&s_cnt, 1)] = (((unsigned long long)bz) << 17) | (unsigned long long)(0x1FFFFu - (unsigned)(base + 2));
            if ((bw >> 21) >= t1) buf[atomicAdd(&s_cnt, 1)] = (((unsigned long long)bw) << 17) | (unsigned long long)(0x1FFFFu - (unsigned)(base + 3));
        }
    } else {
        // ---- SLOW PATH (rare): level-2 refine on the boundary bin ----
        sh[tid] = 0; sh[tid + 1024] = 0;
        __syncthreads();
        for (int i = tid; i < NN; i += 1024) {
            unsigned bits = __float_as_uint(sc[i]);
            if ((bits >> 21) == t1) hist_add(sh, (bits >> 10) & (NBINS - 1));
        }
        __syncthreads();
        #pragma unroll
        for (int d = 1; d < NBINS; d <<= 1) {
            int v0 = (tid + d < NBINS) ? sh[tid + d] : 0;
            int v1 = (tid + 1024 + d < NBINS) ? sh[tid + 1024 + d] : 0;
            __syncthreads();
            sh[tid] += v0;
            sh[tid + 1024] += v1;
            __syncthreads();
        }
        {
            int i = tid;
            if (chi + sh[i] >= TOPK && (i == NBINS - 1 || chi + sh[i + 1] < TOPK)) s_u = i;
            i = tid + 1024;
            if (chi + sh[i] >= TOPK && (i == NBINS - 1 || chi + sh[i + 1] < TOPK)) s_u = i;
        }
        __syncthreads();
        unsigned thr22 = (t1 << 11) | (unsigned)s_u;
        for (int i = tid; i < NN; i += 1024) {
            unsigned bits = __float_as_uint(sc[i]);
            if ((bits >> 10) >= thr22) {
                int p = atomicAdd(&s_cnt, 1);
                if (p < CAP)
                    buf[p] = (((unsigned long long)bits) << 17) |
                             (unsigned long long)(0x1FFFFu - (unsigned)i);
            }
        }
    }
    __syncthreads();
    int cnt = s_cnt < CAP ? s_cnt : CAP;

    // ---- rank by counting (keys unique; rank = # keys strictly greater) ----
    if (tid < cnt) {
        unsigned long long mine = buf[tid];
        int rank = 0;
        #pragma unroll 4
        for (int j = 0; j < cnt; j++) rank += (buf[j] > mine);

        if (rank < TOPK) {
            int   idx = 0x1FFFF - (int)(mine & 0x1FFFF);
            float s   = __uint_as_float((unsigned)(mine >> 17));

            int a   = idx / HW;
            int pix = idx - a * HW;
            int h   = pix / WW;
            int w   = pix - h * WW;

            const float* bb = box + ((size_t)(b * NA + a) * 4) * HW + pix;
            float tx = bb[0];
            float ty = bb[HW];
            float tw = bb[2 * HW];
            float th = bb[3 * HW];

            float cx = (sigmoidf_(tx) + (float)w) / (float)WW;
            float cy = (sigmoidf_(ty) + (float)h) / (float)HH;
            float spw = fmaxf(tw, 0.0f) + log1pf(expf(-fabsf(tw)));
            float sph = fmaxf(th, 0.0f) + log1pf(expf(-fabsf(th)));
            float bwv = anchors[a * 2 + 0] * spw;
            float bhv = anchors[a * 2 + 1] * sph;
            float clsv = (float)g_cls[(size_t)b * NN + idx];

            float* o = out + ((size_t)b * TOPK + rank) * 6;
            o[0] = s;
            o[1] = clsv;
            o[2] = cx;
            o[3] = cy;
            o[4] = bwv;
            o[5] = bhv;
        }
    }
}

// ---------------- launch ----------------
extern "C" void kernel_launch(void* const* d_in, const int* in_sizes, int n_in,
                              void* d_out, int out_size) {
    const float* box     = (const float*)d_in[0];
    const float* obj     = (const float*)d_in[1];
    const float* quality = (const float*)d_in[2];
    const float* cls     = (const float*)d_in[3];
    const float* anchors = (const float*)d_in[4];
    float* out = (float*)d_out;

    score_kernel<<<(BB * NN / 4 + 255) / 256, 256>>>(obj, quality, cls);
    topk_kernel<<<BB, 1024>>>(box, anchors, out);
}

// round 5
// speedup vs baseline: 1.4826x; 1.4826x over previous
#include <cuda_runtime.h>
#include <stdint.h>

#define BB   8
#define NA   3
#define NC   80
#define HH   160
#define WW   160
#define HW   (HH*WW)        // 25600
#define NN   (NA*HW)        // 76800
#define TOPK 100
#define NBINS 2048
#define CAP  1024

// ---------------- device scratch (no allocations allowed) ----------------
__device__ float    g_scores[BB*NN];
__device__ uint8_t  g_cls[BB*NN];

__device__ __forceinline__ float sigmoidf_(float x) {
    return 1.0f / (1.0f + expf(-x));
}

// ---------------- kernel 1: per-cell score + argmax class (pure streaming) ----------------
// Identical to the 65.5us-run version. At DRAM roofline; do not touch.
__global__ void __launch_bounds__(256) score_kernel(const float* __restrict__ obj,
                                                    const float* __restrict__ quality,
                                                    const float* __restrict__ cls) {
    int t  = blockIdx.x * blockDim.x + threadIdx.x;    // quad index over B*N/4
    int c0 = t * 4;                                    // base cell index
    if (c0 >= BB * NN) return;
    int b   = c0 / NN;
    int r   = c0 - b * NN;
    int a   = r / HW;
    int pix = r - a * HW;                              // multiple of 4

    const float4* cbase = (const float4*)(cls + ((size_t)(b * NA + a) * NC) * HW + pix);
    float m0 = -1e30f, m1 = -1e30f, m2 = -1e30f, m3 = -1e30f;
    int   i0 = 0, i1 = 0, i2 = 0, i3 = 0;
    #pragma unroll 8
    for (int c = 0; c < NC; c++) {
        float4 v = cbase[c * (HW / 4)];
        if (v.x > m0) { m0 = v.x; i0 = c; }
        if (v.y > m1) { m1 = v.y; i1 = c; }
        if (v.z > m2) { m2 = v.z; i2 = c; }
        if (v.w > m3) { m3 = v.w; i3 = c; }
    }

    int oq = (b * NA + a) * HW + pix;
    float4 ov = *(const float4*)(obj + oq);
    float4 qv = *(const float4*)(quality + oq);

    float4 s;
    s.x = sigmoidf_(ov.x) * sigmoidf_(qv.x) * sigmoidf_(m0);
    s.y = sigmoidf_(ov.y) * sigmoidf_(qv.y) * sigmoidf_(m1);
    s.z = sigmoidf_(ov.z) * sigmoidf_(qv.z) * sigmoidf_(m2);
    s.w = sigmoidf_(ov.w) * sigmoidf_(qv.w) * sigmoidf_(m3);

    *(float4*)(g_scores + c0) = s;
    *(uchar4*)(g_cls + c0) = make_uchar4((uint8_t)i0, (uint8_t)i1, (uint8_t)i2, (uint8_t)i3);
}

// ---------------- kernel 2: per-batch top-100 + box decode ----------------
// R2 structure (plain atomics, scalar scans) + fast-path single collect + rank-by-count.
__global__ void __launch_bounds__(1024) topk_kernel(const float* __restrict__ box,
                                                    const float* __restrict__ anchors,
                                                    float* __restrict__ out) {
    __shared__ int                sh[NBINS];
    __shared__ unsigned long long buf[CAP];
    __shared__ int s_cnt, s_t, s_chi, s_tot, s_u;

    int b   = blockIdx.x;
    int tid = threadIdx.x;
    const float* sc = g_scores + (size_t)b * NN;

    // ---- pass A: level-1 histogram (top 11 bits of score) in shared ----
    sh[tid] = 0; sh[tid + 1024] = 0;
    __syncthreads();
    for (int i = tid; i < NN; i += 1024) {
        unsigned bits = __float_as_uint(sc[i]);        // scores in (0,1): sign=0
        atomicAdd(&sh[bits >> 21], 1);
    }
    __syncthreads();

    // ---- parallel inclusive suffix scan (Hillis-Steele) ----
    #pragma unroll
    for (int d = 1; d < NBINS; d <<= 1) {
        int v0 = (tid + d < NBINS) ? sh[tid + d] : 0;
        int v1 = (tid + 1024 + d < NBINS) ? sh[tid + 1024 + d] : 0;
        __syncthreads();
        sh[tid] += v0;
        sh[tid + 1024] += v1;
        __syncthreads();
    }
    // crossing bin: largest i with S[i] >= TOPK
    {
        int i = tid;
        if (sh[i] >= TOPK && (i == NBINS - 1 || sh[i + 1] < TOPK)) {
            s_t = i; s_tot = sh[i]; s_chi = (i < NBINS - 1) ? sh[i + 1] : 0;
        }
        i = tid + 1024;
        if (sh[i] >= TOPK && (i == NBINS - 1 || sh[i + 1] < TOPK)) {
            s_t = i; s_tot = sh[i]; s_chi = (i < NBINS - 1) ? sh[i + 1] : 0;
        }
        if (tid == 0) s_cnt = 0;
    }
    __syncthreads();
    unsigned t1 = (unsigned)s_t;
    int cnt_tot = s_tot;
    int chi     = s_chi;

    if (cnt_tot <= CAP) {
        // ---- FAST PATH: exact candidate count fits; single collect scan ----
        for (int i = tid; i < NN; i += 1024) {
            unsigned bits = __float_as_uint(sc[i]);
            if ((bits >> 21) >= t1) {
                int p = atomicAdd(&s_cnt, 1);
                buf[p] = (((unsigned long long)bits) << 17) |
                         (unsigned long long)(0x1FFFFu - (unsigned)i);
            }
        }
    } else {
        // ---- SLOW PATH: level-2 refine on the boundary bin (R2 behavior) ----
        sh[tid] = 0; sh[tid + 1024] = 0;
        __syncthreads();
        for (int i = tid; i < NN; i += 1024) {
            unsigned bits = __float_as_uint(sc[i]);
            if ((bits >> 21) == t1) atomicAdd(&sh[(bits >> 10) & (NBINS - 1)], 1);
        }
        __syncthreads();
        #pragma unroll
        for (int d = 1; d < NBINS; d <<= 1) {
            int v0 = (tid + d < NBINS) ? sh[tid + d] : 0;
            int v1 = (tid + 1024 + d < NBINS) ? sh[tid + 1024 + d] : 0;
            __syncthreads();
            sh[tid] += v0;
            sh[tid + 1024] += v1;
            __syncthreads();
        }
        {
            int i = tid;
            if (chi + sh[i] >= TOPK && (i == NBINS - 1 || chi + sh[i + 1] < TOPK)) s_u = i;
            i = tid + 1024;
            if (chi + sh[i] >= TOPK && (i == NBINS - 1 || chi + sh[i + 1] < TOPK)) s_u = i;
        }
        __syncthreads();
        unsigned thr22 = (t1 << 11) | (unsigned)s_u;
        for (int i = tid; i < NN; i += 1024) {
            unsigned bits = __float_as_uint(sc[i]);
            if ((bits >> 10) >= thr22) {
                int p = atomicAdd(&s_cnt, 1);
                if (p < CAP)
                    buf[p] = (((unsigned long long)bits) << 17) |
                             (unsigned long long)(0x1FFFFu - (unsigned)i);
            }
        }
    }
    __syncthreads();
    int cnt = s_cnt < CAP ? s_cnt : CAP;

    // ---- rank by counting (keys unique; rank = # keys strictly greater) ----
    if (tid < cnt) {
        unsigned long long mine = buf[tid];
        int rank = 0;
        #pragma unroll 4
        for (int j = 0; j < cnt; j++) rank += (buf[j] > mine);

        if (rank < TOPK) {
            int   idx = 0x1FFFF - (int)(mine & 0x1FFFF);
            float s   = __uint_as_float((unsigned)(mine >> 17));

            int a   = idx / HW;
            int pix = idx - a * HW;
            int h   = pix / WW;
            int w   = pix - h * WW;

            const float* bb = box + ((size_t)(b * NA + a) * 4) * HW + pix;
            float tx = bb[0];
            float ty = bb[HW];
            float tw = bb[2 * HW];
            float th = bb[3 * HW];

            float cx = (sigmoidf_(tx) + (float)w) / (float)WW;
            float cy = (sigmoidf_(ty) + (float)h) / (float)HH;
            float spw = fmaxf(tw, 0.0f) + log1pf(expf(-fabsf(tw)));
            float sph = fmaxf(th, 0.0f) + log1pf(expf(-fabsf(th)));
            float bwv = anchors[a * 2 + 0] * spw;
            float bhv = anchors[a * 2 + 1] * sph;
            float clsv = (float)g_cls[(size_t)b * NN + idx];

            float* o = out + ((size_t)b * TOPK + rank) * 6;
            o[0] = s;
            o[1] = clsv;
            o[2] = cx;
            o[3] = cy;
            o[4] = bwv;
            o[5] = bhv;
        }
    }
}

// ---------------- launch ----------------
extern "C" void kernel_launch(void* const* d_in, const int* in_sizes, int n_in,
                              void* d_out, int out_size) {
    const float* box     = (const float*)d_in[0];
    const float* obj     = (const float*)d_in[1];
    const float* quality = (const float*)d_in[2];
    const float* cls     = (const float*)d_in[3];
    const float* anchors = (const float*)d_in[4];
    float* out = (float*)d_out;

    score_kernel<<<(BB * NN / 4 + 255) / 256, 256>>>(obj, quality, cls);
    topk_kernel<<<BB, 1024>>>(box, anchors, out);
}

// round 6
// speedup vs baseline: 1.9188x; 1.2942x over previous
#include <cuda_runtime.h>
#include <stdint.h>

#define BB   8
#define NA   3
#define NC   80
#define HH   160
#define WW   160
#define HW   (HH*WW)        // 25600
#define NN   (NA*HW)        // 76800
#define TOPK 100
#define NBINS 8192          // 13-bit bins: bits >> 19 (scores < 1.0 -> bits < 2^30)
#define CAP_G 4096
#define SLICES 16
#define TB    (BB*SLICES)   // 128 blocks, all co-resident on 148 SMs
#define SLICE_N (NN/SLICES) // 4800

// ---------------- device scratch (no allocations allowed) ----------------
__device__ float              g_scores[BB*NN];
__device__ uint8_t            g_cls[BB*NN];
__device__ unsigned           g_hist[BB*NBINS];
__device__ unsigned long long g_buf[BB*CAP_G];
__device__ int                g_cnt[BB];
__device__ unsigned           g_bar[2];

__device__ __forceinline__ float sigmoidf_(float x) {
    return 1.0f / (1.0f + expf(-x));
}

// ---------------- kernel 1: score + argmax class + scratch zeroing ----------------
// Streaming body identical to the 65.5us-run version (at DRAM roofline).
__global__ void __launch_bounds__(256) score_kernel(const float* __restrict__ obj,
                                                    const float* __restrict__ quality,
                                                    const float* __restrict__ cls) {
    // zero per-launch scratch (256KB vs 205MB of streaming: free)
    int gt = blockIdx.x * blockDim.x + threadIdx.x;
    for (int i = gt; i < BB * NBINS; i += gridDim.x * blockDim.x) g_hist[i] = 0;
    if (gt < BB) g_cnt[gt] = 0;
    if (gt < 2)  g_bar[gt] = 0;

    int c0 = gt * 4;                                   // base cell index
    if (c0 >= BB * NN) return;
    int b   = c0 / NN;
    int r   = c0 - b * NN;
    int a   = r / HW;
    int pix = r - a * HW;                              // multiple of 4

    const float4* cbase = (const float4*)(cls + ((size_t)(b * NA + a) * NC) * HW + pix);
    float m0 = -1e30f, m1 = -1e30f, m2 = -1e30f, m3 = -1e30f;
    int   i0 = 0, i1 = 0, i2 = 0, i3 = 0;
    #pragma unroll 8
    for (int c = 0; c < NC; c++) {
        float4 v = cbase[c * (HW / 4)];
        if (v.x > m0) { m0 = v.x; i0 = c; }
        if (v.y > m1) { m1 = v.y; i1 = c; }
        if (v.z > m2) { m2 = v.z; i2 = c; }
        if (v.w > m3) { m3 = v.w; i3 = c; }
    }

    int oq = (b * NA + a) * HW + pix;
    float4 ov = *(const float4*)(obj + oq);
    float4 qv = *(const float4*)(quality + oq);

    float4 s;
    s.x = sigmoidf_(ov.x) * sigmoidf_(qv.x) * sigmoidf_(m0);
    s.y = sigmoidf_(ov.y) * sigmoidf_(qv.y) * sigmoidf_(m1);
    s.z = sigmoidf_(ov.z) * sigmoidf_(qv.z) * sigmoidf_(m2);
    s.w = sigmoidf_(ov.w) * sigmoidf_(qv.w) * sigmoidf_(m3);

    *(float4*)(g_scores + c0) = s;
    *(uchar4*)(g_cls + c0) = make_uchar4((uint8_t)i0, (uint8_t)i1, (uint8_t)i2, (uint8_t)i3);
}

// ---------------- grid-wide barrier (all TB blocks co-resident) ----------------
__device__ __forceinline__ void grid_barrier(int slot) {
    __syncthreads();
    if (threadIdx.x == 0) {
        __threadfence();
        atomicAdd(&g_bar[slot], 1u);
        while (atomicAdd(&g_bar[slot], 0u) < (unsigned)TB) { }
        __threadfence();
    }
    __syncthreads();
}

__device__ __forceinline__ unsigned long long make_key(unsigned bits, unsigned idx) {
    return (((unsigned long long)bits) << 17) | (unsigned long long)(0x1FFFFu - idx);
}

__device__ __forceinline__ void decode_write(int b, unsigned long long key, int rank,
                                             const float* __restrict__ box,
                                             const float* __restrict__ anchors,
                                             float* __restrict__ out) {
    int   idx = 0x1FFFF - (int)(key & 0x1FFFF);
    float s   = __uint_as_float((unsigned)(key >> 17));

    int a   = idx / HW;
    int pix = idx - a * HW;
    int h   = pix / WW;
    int w   = pix - h * WW;

    const float* bb = box + ((size_t)(b * NA + a) * 4) * HW + pix;
    float tx = bb[0];
    float ty = bb[HW];
    float tw = bb[2 * HW];
    float th = bb[3 * HW];

    float cx = (sigmoidf_(tx) + (float)w) / (float)WW;
    float cy = (sigmoidf_(ty) + (float)h) / (float)HH;
    float spw = fmaxf(tw, 0.0f) + log1pf(expf(-fabsf(tw)));
    float sph = fmaxf(th, 0.0f) + log1pf(expf(-fabsf(th)));
    float bwv = anchors[a * 2 + 0] * spw;
    float bhv = anchors[a * 2 + 1] * sph;
    float clsv = (float)g_cls[(size_t)b * NN + idx];

    float* o = out + ((size_t)b * TOPK + rank) * 6;
    o[0] = s;
    o[1] = clsv;
    o[2] = cx;
    o[3] = cy;
    o[4] = bwv;
    o[5] = bhv;
}

// ---------------- kernel 2: fused multi-block top-100 + decode ----------------
__global__ void __launch_bounds__(1024) topk_kernel(const float* __restrict__ box,
                                                    const float* __restrict__ anchors,
                                                    float* __restrict__ out) {
    __shared__ __align__(16) unsigned char sh_raw[NBINS * 4];   // 32KB: hist OR candidates
    __shared__ unsigned ss[1024];
    __shared__ int s_t1;

    unsigned*           sh_hist = (unsigned*)sh_raw;
    unsigned long long* cand    = (unsigned long long*)sh_raw;  // CAP_G u64 = 32KB

    int tid   = threadIdx.x;
    int b     = blockIdx.x >> 4;         // batch
    int slice = blockIdx.x & (SLICES - 1);

    const float*  sc  = g_scores + (size_t)b * NN;
    const float4* sl4 = (const float4*)(sc + slice * SLICE_N);

    // ================= phase 1: slice histogram -> global merge =================
    #pragma unroll
    for (int i = tid; i < NBINS; i += 1024) sh_hist[i] = 0;
    __syncthreads();
    for (int i = tid; i < SLICE_N / 4; i += 1024) {
        float4 v = sl4[i];
        atomicAdd(&sh_hist[__float_as_uint(v.x) >> 19], 1u);
        atomicAdd(&sh_hist[__float_as_uint(v.y) >> 19], 1u);
        atomicAdd(&sh_hist[__float_as_uint(v.z) >> 19], 1u);
        atomicAdd(&sh_hist[__float_as_uint(v.w) >> 19], 1u);
    }
    __syncthreads();
    #pragma unroll
    for (int i = tid; i < NBINS; i += 1024) {
        unsigned v = sh_hist[i];
        if (v) atomicAdd(&g_hist[b * NBINS + i], v);
    }

    grid_barrier(0);

    // ================= phase 2: find crossing bin, collect candidates =================
    // load merged hist
    #pragma unroll
    for (int i = tid; i < NBINS; i += 1024) sh_hist[i] = g_hist[b * NBINS + i];
    __syncthreads();

    // per-thread local sums over 8 contiguous bins, then 1024-wide suffix scan
    unsigned local = 0;
    #pragma unroll
    for (int k = 0; k < 8; k++) local += sh_hist[tid * 8 + k];
    ss[tid] = local;
    __syncthreads();
    #pragma unroll
    for (int d = 1; d < 1024; d <<= 1) {
        unsigned v = (tid + d < 1024) ? ss[tid + d] : 0u;
        __syncthreads();
        ss[tid] += v;
        __syncthreads();
    }
    {
        unsigned mine  = ss[tid];                       // sum over bins >= 8*tid
        unsigned below = (tid < 1023) ? ss[tid + 1] : 0u;
        if (mine >= TOPK && below < TOPK) {
            unsigned cum = below;
            #pragma unroll
            for (int k = 7; k >= 0; k--) {
                cum += sh_hist[tid * 8 + k];
                if (cum >= TOPK) { s_t1 = tid * 8 + k; break; }
            }
        }
    }
    __syncthreads();
    unsigned t1 = (unsigned)s_t1;

    // collect from this block's slice into the global candidate buffer
    for (int i = tid; i < SLICE_N / 4; i += 1024) {
        float4 v = sl4[i];
        unsigned bx = __float_as_uint(v.x);
        unsigned by = __float_as_uint(v.y);
        unsigned bz = __float_as_uint(v.z);
        unsigned bw = __float_as_uint(v.w);
        unsigned base = (unsigned)(slice * SLICE_N + i * 4);
        if ((bx >> 19) >= t1) { int p = atomicAdd(&g_cnt[b], 1); if (p < CAP_G) g_buf[b * CAP_G + p] = make_key(bx, base + 0); }
        if ((by >> 19) >= t1) { int p = atomicAdd(&g_cnt[b], 1); if (p < CAP_G) g_buf[b * CAP_G + p] = make_key(by, base + 1); }
        if ((bz >> 19) >= t1) { int p = atomicAdd(&g_cnt[b], 1); if (p < CAP_G) g_buf[b * CAP_G + p] = make_key(bz, base + 2); }
        if ((bw >> 19) >= t1) { int p = atomicAdd(&g_cnt[b], 1); if (p < CAP_G) g_buf[b * CAP_G + p] = make_key(bw, base + 3); }
    }

    grid_barrier(1);

    // ================= phase 3: rank + decode (one block per batch) =================
    if (slice != 0) return;

    int cntg = g_cnt[b];
    if (cntg <= CAP_G) {
        int cnt = cntg;
        for (int i = tid; i < cnt; i += 1024) cand[i] = g_buf[b * CAP_G + i];
        __syncthreads();
        for (int c = tid; c < cnt; c += 1024) {
            unsigned long long mine = cand[c];
            int rank = 0;
            #pragma unroll 4
            for (int j = 0; j < cnt; j++) rank += (cand[j] > mine);
            if (rank < TOPK) decode_write(b, mine, rank, box, anchors, out);
        }
    } else {
        // exact fallback (never expected): 100x repeated max-extraction
        unsigned long long prev = ~0ULL;
        for (int k = 0; k < TOPK; k++) {
            unsigned long long m = 0ULL;
            for (int i = tid; i < NN; i += 1024) {
                unsigned long long key = make_key(__float_as_uint(sc[i]), (unsigned)i);
                if (key < prev && key > m) m = key;
            }
            cand[tid] = m;
            __syncthreads();
            for (int s = 512; s > 0; s >>= 1) {
                if (tid < s && cand[tid + s] > cand[tid]) cand[tid] = cand[tid + s];
                __syncthreads();
            }
            unsigned long long win = cand[0];
            if (tid == 0) decode_write(b, win, k, box, anchors, out);
            prev = win;
            __syncthreads();
        }
    }
}

// ---------------- launch ----------------
extern "C" void kernel_launch(void* const* d_in, const int* in_sizes, int n_in,
                              void* d_out, int out_size) {
    const float* box     = (const float*)d_in[0];
    const float* obj     = (const float*)d_in[1];
    const float* quality = (const float*)d_in[2];
    const float* cls     = (const float*)d_in[3];
    const float* anchors = (const float*)d_in[4];
    float* out = (float*)d_out;

    score_kernel<<<BB * NN / 4 / 256, 256>>>(obj, quality, cls);
    topk_kernel<<<TB, 1024>>>(box, anchors, out);
}